// round 3
// baseline (speedup 1.0000x reference)
#include <cuda_runtime.h>

// Depthwise conv_transpose2d(stride=4, k=7, bilinear) == separable x4 upsample.
// Input  x: [4, 256, 64, 64] fp32, Output: [4, 256, 259, 259] fp32.
//
// One thread per 4x4 output tile. Tile (a,b): output rows 4a..4a+3, cols
// 4b..4b+3, fed by input corners x[{a-1,a},{b-1,b}] (OOB taps = 0).
// Unified weights: out[4a+p] = wA*in[a-1] + (1-wA)*in[a], wA = 0.75-0.25p
// (p=3 degenerates to identity on in[a]); same along x. Separable:
// horizontal blend of the 2 corner rows (4+4 values), then vertical blend.

namespace {
constexpr int H = 64, W = 64;
constexpr int OH = 259, OW = 259;
constexpr int PLANES = 4 * 256;          // 1024
constexpr int TB = 65;                   // tiles per axis (a,b in 0..64)
constexpr int TILES = TB * TB;           // 4225 tiles per plane
constexpr int THREADS = 256;
constexpr int BLK_X = (TILES + THREADS - 1) / THREADS;  // 17
}

__global__ void __launch_bounds__(THREADS)
bilinear_up4_tile_kernel(const float* __restrict__ x, float* __restrict__ out) {
    int tp = blockIdx.x * THREADS + threadIdx.x;
    if (tp >= TILES) return;
    int plane = blockIdx.y;

    int a = tp / TB;                     // y tile
    int b = tp - a * TB;                 // x tile (consecutive across warp)

    const float* __restrict__ xp = x + (size_t)plane * (H * W);

    // ---- 4 corner loads (predicated on bounds; OOB -> 0) ----
    bool rAok = (a >= 1), rBok = (a < H);
    bool cAok = (b >= 1), cBok = (b < W);
    const float* rowA = xp + (a - 1) * W;
    const float* rowB = xp + a * W;

    float vAA = (rAok && cAok) ? __ldg(rowA + b - 1) : 0.0f;
    float vAB = (rAok && cBok) ? __ldg(rowA + b)     : 0.0f;
    float vBA = (rBok && cAok) ? __ldg(rowB + b - 1) : 0.0f;
    float vBB = (rBok && cBok) ? __ldg(rowB + b)     : 0.0f;

    // ---- horizontal blends: h[px] per corner row ----
    float dA = vAA - vAB;                // hA = vAB + wx*dA
    float dB = vBA - vBB;
    float hA[4], hB[4], dh[4];
#pragma unroll
    for (int px = 0; px < 4; px++) {
        float wx = 0.75f - 0.25f * (float)px;
        hA[px] = fmaf(wx, dA, vAB);
        hB[px] = fmaf(wx, dB, vBB);
        dh[px] = hA[px] - hB[px];        // out = hB + wy*dh
    }

    // ---- vertical blends + stores ----
    float* dst = out + (size_t)plane * ((size_t)OH * OW)
                     + (size_t)(4 * a) * OW + 4 * b;

    if (a < H && b < W) {
        // interior fast path: all 16 in-bounds, no predicates
#pragma unroll
        for (int py = 0; py < 4; py++) {
            float wy = 0.75f - 0.25f * (float)py;
            float* r = dst + py * OW;
            r[0] = fmaf(wy, dh[0], hB[0]);
            r[1] = fmaf(wy, dh[1], hB[1]);
            r[2] = fmaf(wy, dh[2], hB[2]);
            r[3] = fmaf(wy, dh[3], hB[3]);
        }
    } else {
        // edge tiles (a==64 or b==64): only oy/ox < 259 valid
#pragma unroll
        for (int py = 0; py < 4; py++) {
            int oy = 4 * a + py;
            if (oy >= OH) break;
            float wy = 0.75f - 0.25f * (float)py;
            float* r = dst + py * OW;
#pragma unroll
            for (int px = 0; px < 4; px++) {
                if (4 * b + px < OW)
                    r[px] = fmaf(wy, dh[px], hB[px]);
            }
        }
    }
}

extern "C" void kernel_launch(void* const* d_in, const int* in_sizes, int n_in,
                              void* d_out, int out_size) {
    const float* x = (const float*)d_in[0];
    float* out = (float*)d_out;
    (void)in_sizes; (void)n_in; (void)out_size;

    dim3 grid(BLK_X, PLANES);
    bilinear_up4_tile_kernel<<<grid, THREADS>>>(x, out);
}

// round 4
// speedup vs baseline: 1.8774x; 1.8774x over previous
#include <cuda_runtime.h>

// Depthwise conv_transpose2d(stride=4, k=7, bilinear) == separable x4 upsample.
// Input  x: [4, 256, 64, 64] fp32, Output: [4, 256, 259, 259] fp32.
//
// Unified tap algebra (p = o & 3, cell = o >> 2):
//   out[o] = wA * in[cell-1] + (1-wA) * in[cell],  wA = 0.75 - 0.25*p
// (p=3 -> weight 0 on in[cell-1]; OOB taps read as 0.)
//
// Launch: grid = (65 y-blocks, 1024 planes), block = 288 threads.
// Thread ox = threadIdx.x handles one output column of a 4-row y-block:
// loads the 4 input corners x[{a-1,a},{b-1,b}], blends horizontally, then
// emits 4 vertically-blended rows. Stores are warp-coalesced (consecutive
// lanes -> consecutive addresses), the property R3 proved is mandatory.

namespace {
constexpr int H = 64, W = 64;
constexpr int OH = 259, OW = 259;
constexpr int AB = 65;                 // y-blocks per plane
constexpr int PLANES = 4 * 256;        // 1024
constexpr int THREADS = 288;           // 9 warps, covers ox 0..258
}

__global__ void __launch_bounds__(THREADS)
bilinear_up4_col_kernel(const float* __restrict__ x, float* __restrict__ out) {
    int ox = threadIdx.x;
    if (ox >= OW) return;
    int a     = blockIdx.x;            // y-block: output rows 4a .. 4a+3
    int plane = blockIdx.y;

    const float* __restrict__ xp = x + plane * (H * W);

    // ---- horizontal taps: columns b-1, b ----
    int b  = ox >> 2;
    int px = ox & 3;
    float wxA = 0.75f - 0.25f * (float)px;   // weight on col b-1 (0 at px==3)

    bool cAok = (b >= 1);                    // b-1 >= 0
    bool cBok = (b < W);                     // b == 64 only at ox==258
    bool rAok = (a >= 1);
    bool rBok = (a < H);                     // a == 64 on last y-block

    const float* rowA = xp + (a - 1) * W;    // input row a-1
    const float* rowB = xp + a * W;          // input row a

    float vAA = (rAok && cAok) ? __ldg(rowA + b - 1) : 0.0f;
    float vAB = (rAok && cBok) ? __ldg(rowA + b)     : 0.0f;
    float vBA = (rBok && cAok) ? __ldg(rowB + b - 1) : 0.0f;
    float vBB = (rBok && cBok) ? __ldg(rowB + b)     : 0.0f;

    // horizontal blends: h = v[b] + wxA * (v[b-1] - v[b])
    float hA = fmaf(wxA, vAA - vAB, vAB);    // from input row a-1
    float hB = fmaf(wxA, vBA - vBB, vBB);    // from input row a
    float dh = hA - hB;                      // out = hB + wy * dh

    // ---- vertical blends -> 4 coalesced row stores ----
    float* o0 = out + (size_t)plane * ((size_t)OH * OW) + (4 * a) * OW + ox;
    o0[0]      = fmaf(0.75f, dh, hB);
    o0[OW]     = fmaf(0.50f, dh, hB);
    o0[2 * OW] = fmaf(0.25f, dh, hB);
    if (a < AB - 1)                          // row 4a+3 valid except last block
        o0[3 * OW] = hB;
}

extern "C" void kernel_launch(void* const* d_in, const int* in_sizes, int n_in,
                              void* d_out, int out_size) {
    const float* x = (const float*)d_in[0];
    float* out = (float*)d_out;
    (void)in_sizes; (void)n_in; (void)out_size;

    dim3 grid(AB, PLANES);                   // 65 x 1024 = 66560 blocks
    bilinear_up4_col_kernel<<<grid, THREADS>>>(x, out);
}

// round 5
// speedup vs baseline: 2.0000x; 1.0653x over previous
#include <cuda_runtime.h>

// Depthwise conv_transpose2d(stride=4, k=7, bilinear) == separable x4 upsample.
// Input  x: [4, 256, 64, 64] fp32, Output: [4, 256, 259, 259] fp32.
//
// Tap algebra (p = o & 3, cell = o >> 2):
//   out[o] = wA * in[cell-1] + (1-wA) * in[cell],  wA = 0.75 - 0.25*p
// (p=3 -> pure in[cell]; OOB taps = 0.)
//
// One block per plane (grid = 1024), 288 threads; thread = one output column
// ox, rolling over all 65 y-blocks. hPrev/hCur hold the horizontal blend of
// input rows a-1 / a in registers; each iteration loads only row a+1's two
// taps (L1-resident after warm-up), then emits 4 coalesced row stores.

namespace {
constexpr int H = 64, W = 64;
constexpr int OH = 259, OW = 259;
constexpr int PLANES = 4 * 256;     // 1024
constexpr int THREADS = 288;        // 9 warps, covers ox 0..258
}

__global__ void __launch_bounds__(THREADS)
bilinear_up4_roll_kernel(const float* __restrict__ x, float* __restrict__ out) {
    int ox = threadIdx.x;
    if (ox >= OW) return;
    int plane = blockIdx.x;

    const float* __restrict__ xp = x + plane * (H * W);
    float* __restrict__ op = out + (size_t)plane * ((size_t)OH * OW) + ox;

    int b  = ox >> 2;
    int px = ox & 3;
    float wxA = 0.75f - 0.25f * (float)px;   // weight on col b-1 (0 at px==3)
    bool cAok = (b >= 1);
    bool cBok = (b < W);                     // b == 64 only at ox == 258

    // h(row -1) = 0; load row 0 and blend.
    float v0 = cAok ? __ldg(xp + b - 1) : 0.0f;
    float v1 = cBok ? __ldg(xp + b)     : 0.0f;
    float hPrev = 0.0f;
    float hCur  = fmaf(wxA, v0 - v1, v1);

#pragma unroll 1
    for (int a = 0; a <= 64; a++) {
        // prefetch input row a+1 (OOB -> 0)
        float n0 = 0.0f, n1 = 0.0f;
        int r = a + 1;
        if (r < H) {
            const float* row = xp + r * W;
            n0 = cAok ? __ldg(row + b - 1) : 0.0f;
            n1 = cBok ? __ldg(row + b)     : 0.0f;
        }

        // 4 output rows for y-block a: out[4a+p] = hCur + wA(p)*(hPrev-hCur)
        float dh = hPrev - hCur;
        float* o0 = op + (size_t)(4 * a) * OW;
        o0[0]      = fmaf(0.75f, dh, hCur);
        o0[OW]     = fmaf(0.50f, dh, hCur);
        o0[2 * OW] = fmaf(0.25f, dh, hCur);
        if (a < 64)
            o0[3 * OW] = hCur;               // oy = 4a+3 (valid while < 259)

        hPrev = hCur;
        hCur  = fmaf(wxA, n0 - n1, n1);
    }
}

extern "C" void kernel_launch(void* const* d_in, const int* in_sizes, int n_in,
                              void* d_out, int out_size) {
    const float* x = (const float*)d_in[0];
    float* out = (float*)d_out;
    (void)in_sizes; (void)n_in; (void)out_size;

    bilinear_up4_roll_kernel<<<PLANES, THREADS>>>(x, out);
}